// round 13
// baseline (speedup 1.0000x reference)
#include <cuda_runtime.h>
#include <cstdint>

#define M_R   12
#define N_E   8
#define C_DIM 1024
#define D_DIM 64
#define B_DIM 32
#define S_DIM 512
#define TS    256
#define THREADS 256

// smem pitches (words). Bank math (32 banks):
//  A frags (32-wide): pitch 36 -> bank = (4*gr + gc) & 31, distinct over 32 lanes
//  W frags:           pitch 72 -> bank = (8*gc + gr) & 31, distinct
//  Z frags (64-wide): pitch 68 -> bank = (4*gr + gc) & 31, distinct (64 cols need pitch >= 64)
#define PA 36
#define PW 72
#define PZ 68

// dynamic smem byte offsets
// Phase 1: SA0+SA1 (2x36864) + SW0+SW1 (2x9216) = 92160
// Phase 2: ZB(69632) + W20/W21 (2x18432) = 106496
//   ZB overlays SA0/SA1 head; W20 starts at 69632 (inside dead SA1/SW regions);
//   all overlays are write-after-sync safe (see barriers below).
#define SA0 0                         // X stage 0: 256*36*4 = 36864
#define SA1 36864                     // X stage 1
#define SW0 73728                     // Wd stage 0: 32*72*4 = 9216
#define SW1 82944                     // Wd stage 1 (ends 92160)
#define ZB  0                         // Z buffer: 256*68*4 = 69632
#define W20 69632                     // Wu stage 0: 64*72*4 = 18432
#define W21 88064                     // Wu stage 1 (ends 106496)
#define SMEM_BYTES 106496

__device__ __forceinline__ uint32_t smem_u32(const void* p) {
    uint32_t a;
    asm("{ .reg .u64 t; cvta.to.shared.u64 t, %1; cvt.u32.u64 %0, t; }" : "=r"(a) : "l"(p));
    return a;
}
__device__ __forceinline__ uint32_t f2tf32(float f) {
    uint32_t u; asm("cvt.rna.tf32.f32 %0, %1;" : "=r"(u) : "f"(f)); return u;
}
__device__ __forceinline__ void cp16(uint32_t dst, const void* src) {
    asm volatile("cp.async.cg.shared.global [%0], [%1], 16;" :: "r"(dst), "l"(src));
}
#define CP_COMMIT() asm volatile("cp.async.commit_group;" ::: "memory")
#define CP_WAIT0()  asm volatile("cp.async.wait_group 0;" ::: "memory")

__device__ __forceinline__ void mma_tf32(float c[4], const uint32_t a[4],
                                         uint32_t b0, uint32_t b1) {
    asm volatile(
        "mma.sync.aligned.m16n8k8.row.col.f32.tf32.tf32.f32 "
        "{%0,%1,%2,%3}, {%4,%5,%6,%7}, {%8,%9}, {%0,%1,%2,%3};\n"
        : "+f"(c[0]), "+f"(c[1]), "+f"(c[2]), "+f"(c[3])
        : "r"(a[0]), "r"(a[1]), "r"(a[2]), "r"(a[3]), "r"(b0), "r"(b1));
}

__global__ __launch_bounds__(THREADS, 2)
void adapter_kernel(const float* __restrict__ x,
                    const int*   __restrict__ eidx,
                    const float* __restrict__ dw,
                    const float* __restrict__ db,
                    const float* __restrict__ uw,
                    float*       __restrict__ out) {
    extern __shared__ float smf[];
    const uint32_t smb = smem_u32(smf);
    __shared__ float sBias[D_DIM];

    const int tid  = threadIdx.x;
    const int lane = tid & 31;
    const int warp = tid >> 5;
    const int gr   = lane >> 2;         // groupID (row within frag)
    const int gc   = lane & 3;          // thread in group (k/col)
    const int wr   = (warp & 3) * 64;   // warp row offset: 4 row-groups x 64
    const int wc   = (warp >> 2) * 32;  // warp col offset: 2 col-groups x 32

    const int m   = blockIdx.x;         // m fastest -> X tile L2-resident across m
    const int bst = blockIdx.y;
    const int b   = bst >> 1;
    const int st  = bst & 1;

    const int e = eidx[m * B_DIM + b];
    const float* xT = x  + ((size_t)b * S_DIM + (size_t)st * TS) * C_DIM;
    const float* wd = dw + (size_t)(m * N_E + e) * C_DIM * D_DIM;
    const float* wu = uw + (size_t)(m * N_E + e) * D_DIM * C_DIM;
    const float* bb = db + (size_t)(m * N_E + e) * D_DIM;
    float* oT = out + (((size_t)m * B_DIM + b) * S_DIM + (size_t)st * TS) * C_DIM;

    if (tid < D_DIM) sBias[tid] = bb[tid];

    // hoisted staging indices (constant per thread)
    const int xrow = tid >> 3, xq = (tid & 7) << 2;        // X: 8 iters of 32 rows
    const int wkr  = tid >> 4, wq = (tid & 15) << 2;       // W: 2/4 iters of 16 k-rows

    // hoisted fragment offsets (word offsets, constant per thread)
    const int aOff = (wr + gr) * PA + gc;                  // + mi*16*PA + kb (+4, +8*PA)
    const int bOff = gc * PW + wc + gr;                    // + kb*PW + ni*8 (+4*PW)
    const int zOff = (wr + gr) * PZ + gc;

    float acc[4][4][4];
#pragma unroll
    for (int mi = 0; mi < 4; ++mi)
#pragma unroll
        for (int ni = 0; ni < 4; ++ni)
#pragma unroll
            for (int j = 0; j < 4; ++j) acc[mi][ni][j] = 0.f;

    // -------- prefetch chunk 0 (raw fp32 via cp.async) --------
    {
#pragma unroll
        for (int i = 0; i < 8; ++i) {       // X [256 rows x 32 k]
            int row = i * 32 + xrow;
            cp16(smb + SA0 + (uint32_t)(row * PA + xq) * 4, xT + (size_t)row * C_DIM + xq);
        }
#pragma unroll
        for (int i = 0; i < 2; ++i) {       // Wd [32 k x 64 d]
            int kr = i * 16 + wkr;
            cp16(smb + SW0 + (uint32_t)(kr * PW + wq) * 4, wd + (size_t)kr * D_DIM + wq);
        }
        CP_COMMIT();
    }

    // ================= Phase 1: D1 = X @ Wd  (32 k-chunks of 32) =================
    // one sync per iteration:
    //   WAIT0 (own copies of chunk kc done) -> SYNC (everyone's copies visible;
    //   all reads of buf cur^1 from iter kc-1 done) -> prefetch kc+1 -> compute kc
    for (int kc = 0; kc < 32; ++kc) {
        const int cur = kc & 1;
        CP_WAIT0();
        __syncthreads();
        if (kc < 31) {
            const int k0 = (kc + 1) * 32;
            const uint32_t na = smb + (cur ? SA0 : SA1);
            const uint32_t nw = smb + (cur ? SW0 : SW1);
#pragma unroll
            for (int i = 0; i < 8; ++i) {
                int row = i * 32 + xrow;
                cp16(na + (uint32_t)(row * PA + xq) * 4, xT + (size_t)row * C_DIM + k0 + xq);
            }
#pragma unroll
            for (int i = 0; i < 2; ++i) {
                int kr = i * 16 + wkr;
                cp16(nw + (uint32_t)(kr * PW + wq) * 4, wd + (size_t)(k0 + kr) * D_DIM + wq);
            }
            CP_COMMIT();
        }
        const float* sA = smf + (cur ? SA1 : SA0) / 4 + aOff;
        const float* sW = smf + (cur ? SW1 : SW0) / 4 + bOff;
#pragma unroll
        for (int kk = 0; kk < 4; ++kk) {
            const int kb = kk * 8;
            uint32_t a[4][4];
#pragma unroll
            for (int mi = 0; mi < 4; ++mi) {
                const float* ap = sA + mi * 16 * PA + kb;
                a[mi][0] = f2tf32(ap[0]);
                a[mi][1] = f2tf32(ap[8 * PA]);
                a[mi][2] = f2tf32(ap[4]);
                a[mi][3] = f2tf32(ap[8 * PA + 4]);
            }
#pragma unroll
            for (int ni = 0; ni < 4; ++ni) {
                const float* bp = sW + kb * PW + ni * 8;
                uint32_t b0 = f2tf32(bp[0]);
                uint32_t b1 = f2tf32(bp[4 * PW]);
#pragma unroll
                for (int mi = 0; mi < 4; ++mi) mma_tf32(acc[mi][ni], a[mi], b0, b1);
            }
        }
    }
    __syncthreads();   // all frag reads done before Z/W20 overwrite SA/SW regions

    // prefetch Wu chunk 0 into W20 (overlays dead SA1/SW0 tails) while epilogue runs
    {
#pragma unroll
        for (int i = 0; i < 4; ++i) {       // Wu [64 d x 64 c]
            int kr = i * 16 + wkr;
            cp16(smb + W20 + (uint32_t)(kr * PW + wq) * 4, wu + (size_t)kr * C_DIM + wq);
        }
        CP_COMMIT();
    }

    // ---- epilogue: Z = swish(D1 + bias) -> zbuf (tf32, pitch 68) ----
    uint32_t* zb = (uint32_t*)smf;
#pragma unroll
    for (int mi = 0; mi < 4; ++mi)
#pragma unroll
        for (int ni = 0; ni < 4; ++ni) {
            int r = wr + mi * 16 + gr;
            int n = wc + ni * 8 + (gc << 1);
            float z0 = acc[mi][ni][0] + sBias[n];
            float z1 = acc[mi][ni][1] + sBias[n + 1];
            float z2 = acc[mi][ni][2] + sBias[n];
            float z3 = acc[mi][ni][3] + sBias[n + 1];
            z0 = z0 / (1.f + __expf(-z0));
            z1 = z1 / (1.f + __expf(-z1));
            z2 = z2 / (1.f + __expf(-z2));
            z3 = z3 / (1.f + __expf(-z3));
            uint2 lo = make_uint2(f2tf32(z0), f2tf32(z1));
            uint2 hi = make_uint2(f2tf32(z2), f2tf32(z3));
            *(uint2*)&zb[r * PZ + n]       = lo;
            *(uint2*)&zb[(r + 8) * PZ + n] = hi;
        }

    // ================= Phase 2: U = Z @ Wu  (16 n-chunks of 64, K=64) =============
    // same one-sync schedule; the iter-0 WAIT0+SYNC also publishes the zb writes
    for (int nc = 0; nc < 16; ++nc) {
        const int cur = nc & 1;
        CP_WAIT0();
        __syncthreads();
        if (nc < 15) {
            const int n0 = (nc + 1) * 64;
            const uint32_t nw = smb + (cur ? W20 : W21);
#pragma unroll
            for (int i = 0; i < 4; ++i) {
                int kr = i * 16 + wkr;
                cp16(nw + (uint32_t)(kr * PW + wq) * 4, wu + (size_t)kr * C_DIM + n0 + wq);
            }
            CP_COMMIT();
        }
        const float* sW = smf + (cur ? W21 : W20) / 4 + bOff;

        float acc2[4][4][4];
#pragma unroll
        for (int mi = 0; mi < 4; ++mi)
#pragma unroll
            for (int ni = 0; ni < 4; ++ni)
#pragma unroll
                for (int j = 0; j < 4; ++j) acc2[mi][ni][j] = 0.f;

#pragma unroll
        for (int kk = 0; kk < 8; ++kk) {
            const int kb = kk * 8;
            uint32_t a[4][4];
#pragma unroll
            for (int mi = 0; mi < 4; ++mi) {     // Z already tf32 — no cvt
                const uint32_t* ap = zb + zOff + mi * 16 * PZ + kb;
                a[mi][0] = ap[0];
                a[mi][1] = ap[8 * PZ];
                a[mi][2] = ap[4];
                a[mi][3] = ap[8 * PZ + 4];
            }
#pragma unroll
            for (int ni = 0; ni < 4; ++ni) {
                const float* bp = sW + kb * PW + ni * 8;
                uint32_t b0 = f2tf32(bp[0]);
                uint32_t b1 = f2tf32(bp[4 * PW]);
#pragma unroll
                for (int mi = 0; mi < 4; ++mi) mma_tf32(acc2[mi][ni], a[mi], b0, b1);
            }
        }

        const int n0 = nc * 64;
#pragma unroll
        for (int mi = 0; mi < 4; ++mi)
#pragma unroll
            for (int ni = 0; ni < 4; ++ni) {
                int r = wr + mi * 16 + gr;
                int n = n0 + wc + ni * 8 + (gc << 1);
                *(float2*)(oT + (size_t)r * C_DIM + n) =
                    make_float2(acc2[mi][ni][0], acc2[mi][ni][1]);
                *(float2*)(oT + (size_t)(r + 8) * C_DIM + n) =
                    make_float2(acc2[mi][ni][2], acc2[mi][ni][3]);
            }
    }
}

extern "C" void kernel_launch(void* const* d_in, const int* in_sizes, int n_in,
                              void* d_out, int out_size) {
    const float* x  = (const float*)d_in[0];
    const int*   e  = (const int*)d_in[1];
    const float* dw = (const float*)d_in[2];
    const float* db = (const float*)d_in[3];
    const float* uw = (const float*)d_in[4];

    cudaFuncSetAttribute(adapter_kernel,
                         cudaFuncAttributeMaxDynamicSharedMemorySize, SMEM_BYTES);

    dim3 grid(M_R, B_DIM * (S_DIM / TS));   // (12, 64) = 768 CTAs
    adapter_kernel<<<grid, THREADS, SMEM_BYTES>>>(x, e, dw, db, uw, (float*)d_out);
}

// round 14
// speedup vs baseline: 1.3760x; 1.3760x over previous
#include <cuda_runtime.h>
#include <cuda_fp16.h>
#include <cstdint>

#define M_R   12
#define N_E   8
#define C_DIM 1024
#define D_DIM 64
#define B_DIM 32
#define S_DIM 512
#define TS    128
#define THREADS 128

// smem pitches (words):
//  X stages  (fp32, LDS.64 at cols 2gc):  pitch 40 -> 8B-unit (4gr+gc) distinct per 16-lane phase
//  W stages  (fp32, LDS.32 at rows 2gc+d): pitch 68 -> bank (8gc+gr) distinct over 32 lanes
//  Z buffer  (fp16x2 words, LDS.32):       pitch 36 -> bank (4gr+gc) distinct over 32 lanes
#define PA 40
#define PW 68
#define PZ 36

// dynamic smem byte offsets
// Phase 1: SA0+SA1 (2x20480) + SW0+SW1 (2x8704) = 58368
// Phase 2: ZB(18432) + W20/W21 (2x17408) = 53248  (ZB overlays SA0, W20 overlays SA1)
#define SA0 0                         // X stage 0: 128*40*4 = 20480
#define SA1 20480                     // X stage 1
#define SW0 40960                     // Wd stage 0: 32*68*4 = 8704
#define SW1 49664                     // Wd stage 1 (ends 58368)
#define ZB  0                         // Z buffer: 128*36*4 = 18432 (fp16x2 packed)
#define W20 20480                     // Wu stage 0: 64*68*4 = 17408
#define W21 40960                     // Wu stage 1 (ends 58368)
#define SMEM_BYTES 58624

__device__ __forceinline__ uint32_t smem_u32(const void* p) {
    uint32_t a;
    asm("{ .reg .u64 t; cvta.to.shared.u64 t, %1; cvt.u32.u64 %0, t; }" : "=r"(a) : "l"(p));
    return a;
}
// pack two fp32 -> fp16x2 (lo = first/lower-k element)
__device__ __forceinline__ uint32_t pk(float lo, float hi) {
    uint32_t d;
    asm("cvt.rn.f16x2.f32 %0, %1, %2;" : "=r"(d) : "f"(hi), "f"(lo));
    return d;
}
__device__ __forceinline__ void cp16(uint32_t dst, const void* src) {
    asm volatile("cp.async.cg.shared.global [%0], [%1], 16;" :: "r"(dst), "l"(src));
}
#define CP_COMMIT() asm volatile("cp.async.commit_group;" ::: "memory")
#define CP_WAIT0()  asm volatile("cp.async.wait_group 0;" ::: "memory")

__device__ __forceinline__ void mma_f16(float c[4], const uint32_t a[4],
                                        uint32_t b0, uint32_t b1) {
    asm volatile(
        "mma.sync.aligned.m16n8k16.row.col.f32.f16.f16.f32 "
        "{%0,%1,%2,%3}, {%4,%5,%6,%7}, {%8,%9}, {%0,%1,%2,%3};\n"
        : "+f"(c[0]), "+f"(c[1]), "+f"(c[2]), "+f"(c[3])
        : "r"(a[0]), "r"(a[1]), "r"(a[2]), "r"(a[3]), "r"(b0), "r"(b1));
}

__global__ __launch_bounds__(THREADS)
void adapter_kernel(const float* __restrict__ x,
                    const int*   __restrict__ eidx,
                    const float* __restrict__ dw,
                    const float* __restrict__ db,
                    const float* __restrict__ uw,
                    float*       __restrict__ out) {
    extern __shared__ float smf[];
    const uint32_t smb = smem_u32(smf);
    __shared__ float sBias[D_DIM];

    const int tid  = threadIdx.x;
    const int lane = tid & 31;
    const int warp = tid >> 5;
    const int gr   = lane >> 2;         // groupID (row within frag)
    const int gc   = lane & 3;          // thread in group
    const int wr   = (warp & 1) * 64;   // warp row offset: 64-row tiles
    const int wc   = (warp >> 1) * 32;  // warp col offset: 32-col tiles

    const int m   = blockIdx.x;         // m fastest -> X tile L2-resident across m
    const int bst = blockIdx.y;
    const int b   = bst >> 2;
    const int st  = bst & 3;

    const int e = eidx[m * B_DIM + b];
    const float* xT = x  + ((size_t)b * S_DIM + (size_t)st * TS) * C_DIM;
    const float* wd = dw + (size_t)(m * N_E + e) * C_DIM * D_DIM;
    const float* wu = uw + (size_t)(m * N_E + e) * D_DIM * C_DIM;
    const float* bb = db + (size_t)(m * N_E + e) * D_DIM;
    float* oT = out + (((size_t)m * B_DIM + b) * S_DIM + (size_t)st * TS) * C_DIM;

    if (tid < D_DIM) sBias[tid] = bb[tid];

    // hoisted staging indices
    const int xrow = tid >> 3, xq = (tid & 7) << 2;        // X: 8 iters of 16 rows
    const int wkr  = tid >> 4, wq = (tid & 15) << 2;       // W: 4/8 iters of 8 k-rows

    // hoisted fragment offsets (word offsets)
    const int aOff = (wr + gr) * PA + 2 * gc;              // + mi*16*PA + kk*16 (+8, +8*PA)
    const int bOff = 2 * gc * PW + wc + gr;                // + kk*16*PW + ni*8 (+PW, +8*PW, +9*PW)
    const int zOff = (wr + gr) * PZ + gc;                  // + mi*16*PZ + kk*8 (+4, +8*PZ)

    float acc[4][4][4];
#pragma unroll
    for (int mi = 0; mi < 4; ++mi)
#pragma unroll
        for (int ni = 0; ni < 4; ++ni)
#pragma unroll
            for (int j = 0; j < 4; ++j) acc[mi][ni][j] = 0.f;

    // -------- prefetch chunk 0 (raw fp32 via cp.async) --------
    {
#pragma unroll
        for (int i = 0; i < 8; ++i) {       // X [128 rows x 32 k]
            int row = i * 16 + xrow;
            cp16(smb + SA0 + (uint32_t)(row * PA + xq) * 4, xT + (size_t)row * C_DIM + xq);
        }
#pragma unroll
        for (int i = 0; i < 4; ++i) {       // Wd [32 k x 64 d]
            int kr = i * 8 + wkr;
            cp16(smb + SW0 + (uint32_t)(kr * PW + wq) * 4, wd + (size_t)kr * D_DIM + wq);
        }
        CP_COMMIT();
    }

    // ================= Phase 1: D1 = X @ Wd  (32 k-chunks of 32) =================
    // WAIT0 (own copies of chunk kc done) -> SYNC (all copies visible; reads of
    // buf cur^1 from iter kc-1 done) -> prefetch kc+1 -> compute kc
    for (int kc = 0; kc < 32; ++kc) {
        const int cur = kc & 1;
        CP_WAIT0();
        __syncthreads();
        if (kc < 31) {
            const int k0 = (kc + 1) * 32;
            const uint32_t na = smb + (cur ? SA0 : SA1);
            const uint32_t nw = smb + (cur ? SW0 : SW1);
#pragma unroll
            for (int i = 0; i < 8; ++i) {
                int row = i * 16 + xrow;
                cp16(na + (uint32_t)(row * PA + xq) * 4, xT + (size_t)row * C_DIM + k0 + xq);
            }
#pragma unroll
            for (int i = 0; i < 4; ++i) {
                int kr = i * 8 + wkr;
                cp16(nw + (uint32_t)(kr * PW + wq) * 4, wd + (size_t)(k0 + kr) * D_DIM + wq);
            }
            CP_COMMIT();
        }
        const float* sA = smf + (cur ? SA1 : SA0) / 4 + aOff;
        const float* sW = smf + (cur ? SW1 : SW0) / 4 + bOff;
#pragma unroll
        for (int kk = 0; kk < 2; ++kk) {    // 2 x k16 per chunk
            uint32_t a[4][4];
#pragma unroll
            for (int mi = 0; mi < 4; ++mi) {
                const float* ap = sA + mi * 16 * PA + kk * 16;
                float2 v0 = *(const float2*)(ap);                  // row gr,   k 2gc..2gc+1
                float2 v1 = *(const float2*)(ap + 8 * PA);         // row gr+8
                float2 v2 = *(const float2*)(ap + 8);              // row gr,   k +8
                float2 v3 = *(const float2*)(ap + 8 * PA + 8);     // row gr+8, k +8
                a[mi][0] = pk(v0.x, v0.y);
                a[mi][1] = pk(v1.x, v1.y);
                a[mi][2] = pk(v2.x, v2.y);
                a[mi][3] = pk(v3.x, v3.y);
            }
#pragma unroll
            for (int ni = 0; ni < 4; ++ni) {
                const float* bp = sW + kk * 16 * PW + ni * 8;
                uint32_t b0 = pk(bp[0], bp[PW]);                   // k 2gc, 2gc+1
                uint32_t b1 = pk(bp[8 * PW], bp[9 * PW]);          // k 2gc+8, 2gc+9
#pragma unroll
                for (int mi = 0; mi < 4; ++mi) mma_f16(acc[mi][ni], a[mi], b0, b1);
            }
        }
    }
    __syncthreads();   // all frag reads done before ZB/W20 overwrite SA0/SA1

    // prefetch Wu chunk 0 into W20 (overlays dead SA1) while epilogue runs
    {
#pragma unroll
        for (int i = 0; i < 8; ++i) {       // Wu [64 d x 64 c]
            int kr = i * 8 + wkr;
            cp16(smb + W20 + (uint32_t)(kr * PW + wq) * 4, wu + (size_t)kr * C_DIM + wq);
        }
        CP_COMMIT();
    }

    // ---- epilogue: Z = swish(D1 + bias) -> zb as packed fp16x2 (pitch 36 words) ----
    uint32_t* zb = (uint32_t*)smf;
#pragma unroll
    for (int mi = 0; mi < 4; ++mi)
#pragma unroll
        for (int ni = 0; ni < 4; ++ni) {
            int r  = wr + mi * 16 + gr;
            int n  = wc + ni * 8 + (gc << 1);
            float z0 = acc[mi][ni][0] + sBias[n];
            float z1 = acc[mi][ni][1] + sBias[n + 1];
            float z2 = acc[mi][ni][2] + sBias[n];
            float z3 = acc[mi][ni][3] + sBias[n + 1];
            z0 = z0 / (1.f + __expf(-z0));
            z1 = z1 / (1.f + __expf(-z1));
            z2 = z2 / (1.f + __expf(-z2));
            z3 = z3 / (1.f + __expf(-z3));
            int w = n >> 1;                    // fp16x2 word index
            zb[r * PZ + w]       = pk(z0, z1);
            zb[(r + 8) * PZ + w] = pk(z2, z3);
        }

    // ================= Phase 2: U = Z @ Wu  (16 n-chunks of 64, K=64) =============
    // same one-sync schedule; iter-0 WAIT0+SYNC also publishes the zb writes
    for (int nc = 0; nc < 16; ++nc) {
        const int cur = nc & 1;
        CP_WAIT0();
        __syncthreads();
        if (nc < 15) {
            const int n0 = (nc + 1) * 64;
            const uint32_t nw = smb + (cur ? W20 : W21);
#pragma unroll
            for (int i = 0; i < 8; ++i) {
                int kr = i * 8 + wkr;
                cp16(nw + (uint32_t)(kr * PW + wq) * 4, wu + (size_t)kr * C_DIM + n0 + wq);
            }
            CP_COMMIT();
        }
        const float* sW = smf + (cur ? W21 : W20) / 4 + bOff;

        float acc2[4][4][4];
#pragma unroll
        for (int mi = 0; mi < 4; ++mi)
#pragma unroll
            for (int ni = 0; ni < 4; ++ni)
#pragma unroll
                for (int j = 0; j < 4; ++j) acc2[mi][ni][j] = 0.f;

#pragma unroll
        for (int kk = 0; kk < 4; ++kk) {    // 4 x k16 (K = 64)
            uint32_t a[4][4];
#pragma unroll
            for (int mi = 0; mi < 4; ++mi) {   // Z pre-packed fp16x2: plain LDS.32, no cvt
                const uint32_t* ap = zb + zOff + mi * 16 * PZ + kk * 8;
                a[mi][0] = ap[0];
                a[mi][1] = ap[8 * PZ];
                a[mi][2] = ap[4];
                a[mi][3] = ap[8 * PZ + 4];
            }
#pragma unroll
            for (int ni = 0; ni < 4; ++ni) {
                const float* bp = sW + kk * 16 * PW + ni * 8;
                uint32_t b0 = pk(bp[0], bp[PW]);
                uint32_t b1 = pk(bp[8 * PW], bp[9 * PW]);
#pragma unroll
                for (int mi = 0; mi < 4; ++mi) mma_f16(acc2[mi][ni], a[mi], b0, b1);
            }
        }

        const int n0 = nc * 64;
#pragma unroll
        for (int mi = 0; mi < 4; ++mi)
#pragma unroll
            for (int ni = 0; ni < 4; ++ni) {
                int r = wr + mi * 16 + gr;
                int n = n0 + wc + ni * 8 + (gc << 1);
                *(float2*)(oT + (size_t)r * C_DIM + n) =
                    make_float2(acc2[mi][ni][0], acc2[mi][ni][1]);
                *(float2*)(oT + (size_t)(r + 8) * C_DIM + n) =
                    make_float2(acc2[mi][ni][2], acc2[mi][ni][3]);
            }
    }
}

extern "C" void kernel_launch(void* const* d_in, const int* in_sizes, int n_in,
                              void* d_out, int out_size) {
    const float* x  = (const float*)d_in[0];
    const int*   e  = (const int*)d_in[1];
    const float* dw = (const float*)d_in[2];
    const float* db = (const float*)d_in[3];
    const float* uw = (const float*)d_in[4];

    cudaFuncSetAttribute(adapter_kernel,
                         cudaFuncAttributeMaxDynamicSharedMemorySize, SMEM_BYTES);

    dim3 grid(M_R, B_DIM * (S_DIM / TS));
    adapter_kernel<<<grid, THREADS, SMEM_BYTES>>>(x, e, dw, db, uw, (float*)d_out);
}

// round 15
// speedup vs baseline: 1.5288x; 1.1111x over previous
#include <cuda_runtime.h>
#include <cuda_fp16.h>
#include <cstdint>

#define M_R   12
#define N_E   8
#define C_DIM 1024
#define D_DIM 64
#define B_DIM 32
#define S_DIM 512
#define TS    128
#define THREADS 128

// fp16 staged pitches (32-bit words per row). Bank math:
//  X/Wd frags: pitch 20 -> bank (gr*20+gc) mod 32 is a permutation over 32 lanes
//  Wu frags:   pitch 36 -> bank (gr*4+gc) distinct
//  Z buffer:   pitch 36 (fp16x2 words)
#define PAH 20
#define PWH 20
#define PW2 36
#define PZ  36

// dynamic smem byte offsets
// Phase 1: SA0/SA1 (2x10240) + SW0/SW1 (2x5120) = 30720
// Phase 2: ZB(18432) + W20/W21 (2x9216) = 36864  (ZB overlays SA0+SA1 head)
#define SA0 0
#define SA1 10240
#define SW0 20480
#define SW1 25600
#define ZB  0
#define W20 18432
#define W21 27648
#define SMEM_BYTES 36864

// fp16 mirrors (converted once per launch by pre-kernels)
__device__ __half g_xh[(size_t)B_DIM * S_DIM * C_DIM];          // [b,s,c]   32 MB
__device__ __half g_wdh[(size_t)M_R * N_E * D_DIM * C_DIM];     // [me][d][k] 12 MB
__device__ __half g_wuh[(size_t)M_R * N_E * C_DIM * D_DIM];     // [me][c][d] 12 MB

__device__ __forceinline__ uint32_t smem_u32(const void* p) {
    uint32_t a;
    asm("{ .reg .u64 t; cvta.to.shared.u64 t, %1; cvt.u32.u64 %0, t; }" : "=r"(a) : "l"(p));
    return a;
}
// pack two fp32 -> fp16x2 word {lo: first, hi: second}
__device__ __forceinline__ uint32_t pk(float lo, float hi) {
    uint32_t d;
    asm("cvt.rn.f16x2.f32 %0, %1, %2;" : "=r"(d) : "f"(hi), "f"(lo));
    return d;
}
__device__ __forceinline__ uint32_t prmt(uint32_t a, uint32_t b, uint32_t sel) {
    uint32_t d;
    asm("prmt.b32 %0, %1, %2, %3;" : "=r"(d) : "r"(a), "r"(b), "r"(sel));
    return d;
}
__device__ __forceinline__ void cp16(uint32_t dst, const void* src) {
    asm volatile("cp.async.cg.shared.global [%0], [%1], 16;" :: "r"(dst), "l"(src));
}
#define CP_COMMIT() asm volatile("cp.async.commit_group;" ::: "memory")
#define CP_WAIT0()  asm volatile("cp.async.wait_group 0;" ::: "memory")

__device__ __forceinline__ void mma_f16(float c[4], const uint32_t a[4],
                                        uint32_t b0, uint32_t b1) {
    asm volatile(
        "mma.sync.aligned.m16n8k16.row.col.f32.f16.f16.f32 "
        "{%0,%1,%2,%3}, {%4,%5,%6,%7}, {%8,%9}, {%0,%1,%2,%3};\n"
        : "+f"(c[0]), "+f"(c[1]), "+f"(c[2]), "+f"(c[3])
        : "r"(a[0]), "r"(a[1]), "r"(a[2]), "r"(a[3]), "r"(b0), "r"(b1));
}

// ---------------- conversion pre-kernels ----------------

__global__ void cvt_x_kernel(const float* __restrict__ x) {
    size_t i = ((size_t)blockIdx.x * 256 + threadIdx.x) * 8;
    float4 v0 = *(const float4*)(x + i);
    float4 v1 = *(const float4*)(x + i + 4);
    uint4 o = make_uint4(pk(v0.x, v0.y), pk(v0.z, v0.w),
                         pk(v1.x, v1.y), pk(v1.z, v1.w));
    *(uint4*)((uint32_t*)g_xh + i / 2) = o;
}

// Wd [me][k=1024][d=64] fp32 -> g_wdh [me][d][k] fp16. 64x64 tiles through smem.
__global__ void cvt_wd_kernel(const float* __restrict__ dw) {
    __shared__ uint32_t tile[64 * 33];   // [k-local][d-pair word]
    const int me = blockIdx.x, kt = blockIdx.y, t = threadIdx.x;
    const float* src = dw + ((size_t)me * 1024 + (size_t)kt * 64) * 64;
#pragma unroll
    for (int i = 0; i < 8; ++i) {
        int lin = i * 256 + t, r = lin >> 5, j = lin & 31;
        float2 v = *(const float2*)(src + r * 64 + 2 * j);
        tile[r * 33 + j] = pk(v.x, v.y);              // {d=2j, d=2j+1}
    }
    __syncthreads();
    uint32_t* dst = (uint32_t*)g_wdh + (size_t)me * 64 * 512 + kt * 32;
#pragma unroll
    for (int i = 0; i < 8; ++i) {
        int lin = i * 256 + t, d = lin >> 5, iw = lin & 31;
        uint32_t a = tile[(2 * iw) * 33 + (d >> 1)];
        uint32_t b = tile[(2 * iw + 1) * 33 + (d >> 1)];
        uint32_t w = (d & 1) ? prmt(a, b, 0x7632) : prmt(a, b, 0x5410);
        dst[(size_t)d * 512 + iw] = w;                // {k=2iw, k=2iw+1} at row d
    }
}

// Wu [me][d=64][c=1024] fp32 -> g_wuh [me][c][d] fp16. 64x64 tiles through smem.
__global__ void cvt_wu_kernel(const float* __restrict__ uw) {
    __shared__ uint32_t tile[64 * 33];   // [d-local][c-pair word]
    const int me = blockIdx.x, ct = blockIdx.y, t = threadIdx.x;
    const float* src = uw + (size_t)me * 64 * 1024 + (size_t)ct * 64;
#pragma unroll
    for (int i = 0; i < 8; ++i) {
        int lin = i * 256 + t, r = lin >> 5, j = lin & 31;   // r = d, j = c-pair
        float2 v = *(const float2*)(src + (size_t)r * 1024 + 2 * j);
        tile[r * 33 + j] = pk(v.x, v.y);              // {c=2j, c=2j+1}
    }
    __syncthreads();
    uint32_t* dst = (uint32_t*)g_wuh + ((size_t)me * 1024 + (size_t)ct * 64) * 32;
#pragma unroll
    for (int i = 0; i < 8; ++i) {
        int lin = i * 256 + t, c = lin >> 5, iw = lin & 31;
        uint32_t a = tile[(2 * iw) * 33 + (c >> 1)];
        uint32_t b = tile[(2 * iw + 1) * 33 + (c >> 1)];
        uint32_t w = (c & 1) ? prmt(a, b, 0x7632) : prmt(a, b, 0x5410);
        dst[(size_t)c * 32 + iw] = w;                 // {d=2iw, d=2iw+1} at row c
    }
}

// ---------------- main kernel ----------------

__global__ __launch_bounds__(THREADS)
void adapter_kernel(const int*   __restrict__ eidx,
                    const float* __restrict__ db,
                    float*       __restrict__ out) {
    extern __shared__ float smf[];
    const uint32_t smb = smem_u32(smf);
    uint32_t* smw = (uint32_t*)smf;
    __shared__ float sBias[D_DIM];

    const int tid  = threadIdx.x;
    const int lane = tid & 31;
    const int warp = tid >> 5;
    const int gr   = lane >> 2;
    const int gc   = lane & 3;
    const int wr   = (warp & 1) * 64;   // warp row offset
    const int wc   = (warp >> 1) * 32;  // warp col offset

    const int m   = blockIdx.x;         // m fastest -> X tile L2-resident across m
    const int bst = blockIdx.y;
    const int b   = bst >> 2;
    const int st  = bst & 3;

    const int e  = eidx[m * B_DIM + b];
    const int me = m * N_E + e;
    const __half* xT = g_xh  + ((size_t)b * S_DIM + (size_t)st * TS) * C_DIM;
    const __half* wd = g_wdh + (size_t)me * D_DIM * C_DIM;   // [d][k]
    const __half* wu = g_wuh + (size_t)me * C_DIM * D_DIM;   // [c][d]
    const float*  bb = db + (size_t)me * D_DIM;
    float* oT = out + (((size_t)m * B_DIM + b) * S_DIM + (size_t)st * TS) * C_DIM;

    if (tid < D_DIM) sBias[tid] = bb[tid];

    // staging indices (16B = 8 halves per cp16)
    const int xrow = tid >> 2, xq = tid & 3;        // X: 4 iters of 32 rows, 4 quads/row
    const int wn   = tid >> 2, wq = tid & 3;        // Wd: 2 iters of 32 n-rows
    const int un   = tid >> 3, uq = tid & 7;        // Wu: 4 iters of 16 n-rows, 8 quads

    // fragment word offsets
    const int aOff = (wr + gr) * PAH + gc;          // + mi*16*PAH + kk*8 (+4, +8*PAH)
    const int bOff = (wc + gr) * PWH + gc;          // + ni*8*PWH + kk*8 (+4)
    const int b2Off = (wc + gr) * PW2 + gc;         // phase 2 Wu
    const int zOff  = (wr + gr) * PZ + gc;

    float acc[4][4][4];
#pragma unroll
    for (int mi = 0; mi < 4; ++mi)
#pragma unroll
        for (int ni = 0; ni < 4; ++ni)
#pragma unroll
            for (int j = 0; j < 4; ++j) acc[mi][ni][j] = 0.f;

    // -------- prefetch chunk 0 (fp16) --------
    {
#pragma unroll
        for (int i = 0; i < 4; ++i) {       // X [128 rows x 32 k] = 512 cp16
            int row = i * 32 + xrow;
            cp16(smb + SA0 + (uint32_t)(row * PAH + xq * 4) * 4,
                 xT + (size_t)row * C_DIM + xq * 8);
        }
#pragma unroll
        for (int i = 0; i < 2; ++i) {       // Wd^T [64 n x 32 k] = 256 cp16
            int n = i * 32 + wn;
            cp16(smb + SW0 + (uint32_t)(n * PWH + wq * 4) * 4,
                 wd + (size_t)n * C_DIM + wq * 8);
        }
        CP_COMMIT();
    }

    // ================= Phase 1: D1 = X @ Wd  (32 k-chunks of 32) =================
    for (int kc = 0; kc < 32; ++kc) {
        const int cur = kc & 1;
        CP_WAIT0();
        __syncthreads();
        if (kc < 31) {
            const int k0 = (kc + 1) * 32;
            const uint32_t na = smb + (cur ? SA0 : SA1);
            const uint32_t nw = smb + (cur ? SW0 : SW1);
#pragma unroll
            for (int i = 0; i < 4; ++i) {
                int row = i * 32 + xrow;
                cp16(na + (uint32_t)(row * PAH + xq * 4) * 4,
                     xT + (size_t)row * C_DIM + k0 + xq * 8);
            }
#pragma unroll
            for (int i = 0; i < 2; ++i) {
                int n = i * 32 + wn;
                cp16(nw + (uint32_t)(n * PWH + wq * 4) * 4,
                     wd + (size_t)n * C_DIM + k0 + wq * 8);
            }
            CP_COMMIT();
        }
        const uint32_t* sA = smw + (cur ? SA1 : SA0) / 4 + aOff;
        const uint32_t* sW = smw + (cur ? SW1 : SW0) / 4 + bOff;
#pragma unroll
        for (int kk = 0; kk < 2; ++kk) {    // 2 x k16 per chunk
            uint32_t a[4][4];
#pragma unroll
            for (int mi = 0; mi < 4; ++mi) {
                const uint32_t* ap = sA + mi * 16 * PAH + kk * 8;
                a[mi][0] = ap[0];
                a[mi][1] = ap[8 * PAH];
                a[mi][2] = ap[4];
                a[mi][3] = ap[8 * PAH + 4];
            }
#pragma unroll
            for (int ni = 0; ni < 4; ++ni) {
                const uint32_t* bp = sW + ni * 8 * PWH + kk * 8;
                uint32_t b0 = bp[0];
                uint32_t b1 = bp[4];
#pragma unroll
                for (int mi = 0; mi < 4; ++mi) mma_f16(acc[mi][ni], a[mi], b0, b1);
            }
        }
    }
    __syncthreads();   // all frag reads done before ZB/W20 overwrite

    // prefetch Wu chunk 0 into W20 while epilogue runs
    {
#pragma unroll
        for (int i = 0; i < 4; ++i) {       // Wu^T [64 n x 64 d] = 512 cp16
            int n = i * 16 + un;
            cp16(smb + W20 + (uint32_t)(n * PW2 + uq * 4) * 4,
                 wu + (size_t)n * D_DIM + uq * 8);
        }
        CP_COMMIT();
    }

    // ---- epilogue: Z = swish(D1 + bias) -> zb as packed fp16x2 (pitch 36) ----
    uint32_t* zb = smw;
#pragma unroll
    for (int mi = 0; mi < 4; ++mi)
#pragma unroll
        for (int ni = 0; ni < 4; ++ni) {
            int r = wr + mi * 16 + gr;
            int n = wc + ni * 8 + (gc << 1);
            float z0 = acc[mi][ni][0] + sBias[n];
            float z1 = acc[mi][ni][1] + sBias[n + 1];
            float z2 = acc[mi][ni][2] + sBias[n];
            float z3 = acc[mi][ni][3] + sBias[n + 1];
            z0 = z0 / (1.f + __expf(-z0));
            z1 = z1 / (1.f + __expf(-z1));
            z2 = z2 / (1.f + __expf(-z2));
            z3 = z3 / (1.f + __expf(-z3));
            int w = n >> 1;
            zb[r * PZ + w]       = pk(z0, z1);
            zb[(r + 8) * PZ + w] = pk(z2, z3);
        }

    // ================= Phase 2: U = Z @ Wu  (16 n-chunks of 64, K=64) =============
    for (int nc = 0; nc < 16; ++nc) {
        const int cur = nc & 1;
        CP_WAIT0();
        __syncthreads();
        if (nc < 15) {
            const int n0 = (nc + 1) * 64;
            const uint32_t nw = smb + (cur ? W20 : W21);
#pragma unroll
            for (int i = 0; i < 4; ++i) {
                int n = i * 16 + un;
                cp16(nw + (uint32_t)(n * PW2 + uq * 4) * 4,
                     wu + (size_t)(n0 + n) * D_DIM + uq * 8);
            }
            CP_COMMIT();
        }
        const uint32_t* sW = smw + (cur ? W21 : W20) / 4 + b2Off;

        float acc2[4][4][4];
#pragma unroll
        for (int mi = 0; mi < 4; ++mi)
#pragma unroll
            for (int ni = 0; ni < 4; ++ni)
#pragma unroll
                for (int j = 0; j < 4; ++j) acc2[mi][ni][j] = 0.f;

#pragma unroll
        for (int kk = 0; kk < 4; ++kk) {    // 4 x k16 (K = 64)
            uint32_t a[4][4];
#pragma unroll
            for (int mi = 0; mi < 4; ++mi) {
                const uint32_t* ap = zb + zOff + mi * 16 * PZ + kk * 8;
                a[mi][0] = ap[0];
                a[mi][1] = ap[8 * PZ];
                a[mi][2] = ap[4];
                a[mi][3] = ap[8 * PZ + 4];
            }
#pragma unroll
            for (int ni = 0; ni < 4; ++ni) {
                const uint32_t* bp = sW + ni * 8 * PW2 + kk * 8;
                uint32_t b0 = bp[0];
                uint32_t b1 = bp[4];
#pragma unroll
                for (int mi = 0; mi < 4; ++mi) mma_f16(acc2[mi][ni], a[mi], b0, b1);
            }
        }

        const int n0 = nc * 64;
#pragma unroll
        for (int mi = 0; mi < 4; ++mi)
#pragma unroll
            for (int ni = 0; ni < 4; ++ni) {
                int r = wr + mi * 16 + gr;
                int n = n0 + wc + ni * 8 + (gc << 1);
                *(float2*)(oT + (size_t)r * C_DIM + n) =
                    make_float2(acc2[mi][ni][0], acc2[mi][ni][1]);
                *(float2*)(oT + (size_t)(r + 8) * C_DIM + n) =
                    make_float2(acc2[mi][ni][2], acc2[mi][ni][3]);
            }
    }
}

extern "C" void kernel_launch(void* const* d_in, const int* in_sizes, int n_in,
                              void* d_out, int out_size) {
    const float* x  = (const float*)d_in[0];
    const int*   e  = (const int*)d_in[1];
    const float* dw = (const float*)d_in[2];
    const float* db = (const float*)d_in[3];
    const float* uw = (const float*)d_in[4];

    // convert inputs to fp16 mirrors (runs every replay; deterministic)
    cvt_x_kernel<<<(B_DIM * S_DIM * C_DIM) / (256 * 8), 256>>>(x);
    cvt_wd_kernel<<<dim3(M_R * N_E, C_DIM / 64), 256>>>(dw);
    cvt_wu_kernel<<<dim3(M_R * N_E, C_DIM / 64), 256>>>(uw);

    cudaFuncSetAttribute(adapter_kernel,
                         cudaFuncAttributeMaxDynamicSharedMemorySize, SMEM_BYTES);

    dim3 grid(M_R, B_DIM * (S_DIM / TS));
    adapter_kernel<<<grid, THREADS, SMEM_BYTES>>>(e, db, (float*)d_out);
}

// round 17
// speedup vs baseline: 1.5310x; 1.0014x over previous
#include <cuda_runtime.h>
#include <cuda_fp16.h>
#include <cstdint>

#define M_R   12
#define N_E   8
#define C_DIM 1024
#define D_DIM 64
#define B_DIM 32
#define S_DIM 512
#define TS    128
#define THREADS 128

// fp16 staged pitches (32-bit words per row):
//  X/Wd frags: pitch 20 -> bank (gr*20+gc) mod 32 is a permutation over 32 lanes
//  Wu frags:   pitch 36 -> bank (gr*4+gc) distinct
//  Z buffer:   pitch 36 (fp16x2 words)
#define PAH 20
#define PWH 20
#define PW2 36
#define PZ  36

// dynamic smem byte offsets — 3-stage pipelines
// Phase 1: 3 X stages (10240) + 3 Wd stages (5120) = 46080
// Phase 2: ZB(18432) + 3 Wu stages (9216) = 46080  (overlays phase-1 regions)
#define SA0 0                         // X stages: 0, 10240, 20480  (2560 words each)
#define SW0 30720                     // Wd stages: 30720, 35840, 40960 (1280 words each)
#define ZB  0
#define W20 18432                     // Wu stages: 18432, 27648, 36864 (2304 words each)
#define SMEM_BYTES 46080

// fp16 mirrors (converted once per launch by pre-kernels)
__device__ __half g_xh[(size_t)B_DIM * S_DIM * C_DIM];          // [b,s,c]   32 MB
__device__ __half g_wdh[(size_t)M_R * N_E * D_DIM * C_DIM];     // [me][d][k] 12 MB
__device__ __half g_wuh[(size_t)M_R * N_E * C_DIM * D_DIM];     // [me][c][d] 12 MB

__device__ __forceinline__ uint32_t smem_u32(const void* p) {
    uint32_t a;
    asm("{ .reg .u64 t; cvta.to.shared.u64 t, %1; cvt.u32.u64 %0, t; }" : "=r"(a) : "l"(p));
    return a;
}
__device__ __forceinline__ uint32_t pk(float lo, float hi) {
    uint32_t d;
    asm("cvt.rn.f16x2.f32 %0, %1, %2;" : "=r"(d) : "f"(hi), "f"(lo));
    return d;
}
__device__ __forceinline__ uint32_t prmt(uint32_t a, uint32_t b, uint32_t sel) {
    uint32_t d;
    asm("prmt.b32 %0, %1, %2, %3;" : "=r"(d) : "r"(a), "r"(b), "r"(sel));
    return d;
}
__device__ __forceinline__ void cp16(uint32_t dst, const void* src) {
    asm volatile("cp.async.cg.shared.global [%0], [%1], 16;" :: "r"(dst), "l"(src));
}
#define CP_COMMIT() asm volatile("cp.async.commit_group;" ::: "memory")
#define CP_WAIT0()  asm volatile("cp.async.wait_group 0;" ::: "memory")
#define CP_WAIT1()  asm volatile("cp.async.wait_group 1;" ::: "memory")

__device__ __forceinline__ void mma_f16(float c[4], const uint32_t a[4],
                                        uint32_t b0, uint32_t b1) {
    asm volatile(
        "mma.sync.aligned.m16n8k16.row.col.f32.f16.f16.f32 "
        "{%0,%1,%2,%3}, {%4,%5,%6,%7}, {%8,%9}, {%0,%1,%2,%3};\n"
        : "+f"(c[0]), "+f"(c[1]), "+f"(c[2]), "+f"(c[3])
        : "r"(a[0]), "r"(a[1]), "r"(a[2]), "r"(a[3]), "r"(b0), "r"(b1));
}

// ---------------- conversion pre-kernels ----------------

__global__ void cvt_x_kernel(const float* __restrict__ x) {
    size_t i = ((size_t)blockIdx.x * 256 + threadIdx.x) * 8;
    float4 v0 = *(const float4*)(x + i);
    float4 v1 = *(const float4*)(x + i + 4);
    uint4 o = make_uint4(pk(v0.x, v0.y), pk(v0.z, v0.w),
                         pk(v1.x, v1.y), pk(v1.z, v1.w));
    *(uint4*)((uint32_t*)g_xh + i / 2) = o;
}

// Wd [me][k=1024][d=64] fp32 -> g_wdh [me][d][k] fp16. 64x64 tiles through smem.
__global__ void cvt_wd_kernel(const float* __restrict__ dw) {
    __shared__ uint32_t tile[64 * 33];
    const int me = blockIdx.x, kt = blockIdx.y, t = threadIdx.x;
    const float* src = dw + ((size_t)me * 1024 + (size_t)kt * 64) * 64;
#pragma unroll
    for (int i = 0; i < 8; ++i) {
        int lin = i * 256 + t, r = lin >> 5, j = lin & 31;
        float2 v = *(const float2*)(src + r * 64 + 2 * j);
        tile[r * 33 + j] = pk(v.x, v.y);              // {d=2j, d=2j+1}
    }
    __syncthreads();
    uint32_t* dst = (uint32_t*)g_wdh + (size_t)me * 64 * 512 + kt * 32;
#pragma unroll
    for (int i = 0; i < 8; ++i) {
        int lin = i * 256 + t, d = lin >> 5, iw = lin & 31;
        uint32_t a = tile[(2 * iw) * 33 + (d >> 1)];
        uint32_t b = tile[(2 * iw + 1) * 33 + (d >> 1)];
        uint32_t w = (d & 1) ? prmt(a, b, 0x7632) : prmt(a, b, 0x5410);
        dst[(size_t)d * 512 + iw] = w;                // {k=2iw, k=2iw+1} at row d
    }
}

// Wu [me][d=64][c=1024] fp32 -> g_wuh [me][c][d] fp16. 64x64 tiles through smem.
__global__ void cvt_wu_kernel(const float* __restrict__ uw) {
    __shared__ uint32_t tile[64 * 33];
    const int me = blockIdx.x, ct = blockIdx.y, t = threadIdx.x;
    const float* src = uw + (size_t)me * 64 * 1024 + (size_t)ct * 64;
#pragma unroll
    for (int i = 0; i < 8; ++i) {
        int lin = i * 256 + t, r = lin >> 5, j = lin & 31;   // r = d, j = c-pair
        float2 v = *(const float2*)(src + (size_t)r * 1024 + 2 * j);
        tile[r * 33 + j] = pk(v.x, v.y);              // {c=2j, c=2j+1}
    }
    __syncthreads();
    uint32_t* dst = (uint32_t*)g_wuh + ((size_t)me * 1024 + (size_t)ct * 64) * 32;
#pragma unroll
    for (int i = 0; i < 8; ++i) {
        int lin = i * 256 + t, c = lin >> 5, iw = lin & 31;
        uint32_t a = tile[(2 * iw) * 33 + (c >> 1)];
        uint32_t b = tile[(2 * iw + 1) * 33 + (c >> 1)];
        uint32_t w = (c & 1) ? prmt(a, b, 0x7632) : prmt(a, b, 0x5410);
        dst[(size_t)c * 32 + iw] = w;                 // {d=2iw, d=2iw+1} at row c
    }
}

// ---------------- main kernel ----------------

__global__ __launch_bounds__(THREADS)
void adapter_kernel(const int*   __restrict__ eidx,
                    const float* __restrict__ db,
                    float*       __restrict__ out) {
    extern __shared__ float smf[];
    const uint32_t smb = smem_u32(smf);
    uint32_t* smw = (uint32_t*)smf;
    __shared__ float sBias[D_DIM];

    const int tid  = threadIdx.x;
    const int lane = tid & 31;
    const int warp = tid >> 5;
    const int gr   = lane >> 2;
    const int gc   = lane & 3;
    const int wr   = (warp & 1) * 64;
    const int wc   = (warp >> 1) * 32;

    const int m   = blockIdx.x;         // m fastest -> X tile L2-resident across m
    const int bst = blockIdx.y;
    const int b   = bst >> 2;
    const int st  = bst & 3;

    const int e  = eidx[m * B_DIM + b];
    const int me = m * N_E + e;
    const __half* xT = g_xh  + ((size_t)b * S_DIM + (size_t)st * TS) * C_DIM;
    const __half* wd = g_wdh + (size_t)me * D_DIM * C_DIM;   // [d][k]
    const __half* wu = g_wuh + (size_t)me * C_DIM * D_DIM;   // [c][d]
    const float*  bb = db + (size_t)me * D_DIM;
    float* oT = out + (((size_t)m * B_DIM + b) * S_DIM + (size_t)st * TS) * C_DIM;

    if (tid < D_DIM) sBias[tid] = bb[tid];

    // staging indices (16B = 8 halves per cp16)
    const int xrow = tid >> 2, xq = tid & 3;        // X: 4 iters of 32 rows
    const int wn   = tid >> 2, wq = tid & 3;        // Wd: 2 iters of 32 n-rows
    const int un   = tid >> 3, uq = tid & 7;        // Wu: 4 iters of 16 n-rows

    // fragment word offsets
    const int aOff  = (wr + gr) * PAH + gc;
    const int bOff  = (wc + gr) * PWH + gc;
    const int b2Off = (wc + gr) * PW2 + gc;
    const int zOff  = (wr + gr) * PZ + gc;

    float acc[4][4][4];
#pragma unroll
    for (int mi = 0; mi < 4; ++mi)
#pragma unroll
        for (int ni = 0; ni < 4; ++ni)
#pragma unroll
            for (int j = 0; j < 4; ++j) acc[mi][ni][j] = 0.f;

    // staging helpers (stage strides: X 2560 words, Wd 1280 words, Wu 2304 words)
    auto stageP1 = [&](int chunk, int stg) {
        const int k0 = chunk * 32;
        const uint32_t na = smb + SA0 + (uint32_t)stg * 10240;
        const uint32_t nw = smb + SW0 + (uint32_t)stg * 5120;
#pragma unroll
        for (int i = 0; i < 4; ++i) {
            int row = i * 32 + xrow;
            cp16(na + (uint32_t)(row * PAH + xq * 4) * 4,
                 xT + (size_t)row * C_DIM + k0 + xq * 8);
        }
#pragma unroll
        for (int i = 0; i < 2; ++i) {
            int n = i * 32 + wn;
            cp16(nw + (uint32_t)(n * PWH + wq * 4) * 4,
                 wd + (size_t)n * C_DIM + k0 + wq * 8);
        }
        CP_COMMIT();
    };
    auto stageP2 = [&](int chunk, int stg) {
        const int n0 = chunk * 64;
        const uint32_t nw = smb + W20 + (uint32_t)stg * 9216;
#pragma unroll
        for (int i = 0; i < 4; ++i) {
            int n = i * 16 + un;
            cp16(nw + (uint32_t)(n * PW2 + uq * 4) * 4,
                 wu + (size_t)(n0 + n) * D_DIM + uq * 8);
        }
        CP_COMMIT();
    };

    // -------- prologue: commit chunks 0 and 1 (separate groups) --------
    stageP1(0, 0);
    stageP1(1, 1);

    // ================= Phase 1: D1 = X @ Wd  (32 k-chunks of 32, 3-stage) =========
    for (int kc = 0; kc < 32; ++kc) {
        const int cur = kc % 3;
        if (kc < 30) CP_WAIT1(); else CP_WAIT0();   // chunk kc complete (own copies)
        __syncthreads();                            // all copies visible; stage (kc+2)%3
                                                    // reads (iter kc-1) done
        if (kc < 30) stageP1(kc + 2, (kc + 2) % 3);

        const uint32_t* sA = smw + SA0 / 4 + cur * 2560 + aOff;
        const uint32_t* sW = smw + SW0 / 4 + cur * 1280 + bOff;
#pragma unroll
        for (int kk = 0; kk < 2; ++kk) {
            uint32_t a[4][4];
#pragma unroll
            for (int mi = 0; mi < 4; ++mi) {
                const uint32_t* ap = sA + mi * 16 * PAH + kk * 8;
                a[mi][0] = ap[0];
                a[mi][1] = ap[8 * PAH];
                a[mi][2] = ap[4];
                a[mi][3] = ap[8 * PAH + 4];
            }
#pragma unroll
            for (int ni = 0; ni < 4; ++ni) {
                const uint32_t* bp = sW + ni * 8 * PWH + kk * 8;
                uint32_t b0 = bp[0];
                uint32_t b1 = bp[4];
#pragma unroll
                for (int mi = 0; mi < 4; ++mi) mma_f16(acc[mi][ni], a[mi], b0, b1);
            }
        }
    }
    __syncthreads();   // all frag reads done before ZB/W2 stages overwrite

    // prologue for phase 2: commit Wu chunks 0 and 1 while epilogue runs
    stageP2(0, 0);
    stageP2(1, 1);

    // ---- epilogue: Z = swish(D1 + bias) -> zb as packed fp16x2 (pitch 36) ----
    uint32_t* zb = smw;
#pragma unroll
    for (int mi = 0; mi < 4; ++mi)
#pragma unroll
        for (int ni = 0; ni < 4; ++ni) {
            int r = wr + mi * 16 + gr;
            int n = wc + ni * 8 + (gc << 1);
            float z0 = acc[mi][ni][0] + sBias[n];
            float z1 = acc[mi][ni][1] + sBias[n + 1];
            float z2 = acc[mi][ni][2] + sBias[n];
            float z3 = acc[mi][ni][3] + sBias[n + 1];
            z0 = z0 / (1.f + __expf(-z0));
            z1 = z1 / (1.f + __expf(-z1));
            z2 = z2 / (1.f + __expf(-z2));
            z3 = z3 / (1.f + __expf(-z3));
            int w = n >> 1;
            zb[r * PZ + w]       = pk(z0, z1);
            zb[(r + 8) * PZ + w] = pk(z2, z3);
        }

    // ================= Phase 2: U = Z @ Wu  (16 n-chunks of 64, 3-stage) ==========
    for (int nc = 0; nc < 16; ++nc) {
        const int cur = nc % 3;
        if (nc < 14) CP_WAIT1(); else CP_WAIT0();
        __syncthreads();                 // publishes zb (iter 0) + chunk nc copies
        if (nc < 14) stageP2(nc + 2, (nc + 2) % 3);

        const uint32_t* sW = smw + W20 / 4 + cur * 2304 + b2Off;

        float acc2[4][4][4];
#pragma unroll
        for (int mi = 0; mi < 4; ++mi)
#pragma unroll
            for (int ni = 0; ni < 4; ++ni)
#pragma unroll
                for (int j = 0; j < 4; ++j) acc2[mi][ni][j] = 0.f;

#pragma unroll
        for (int kk = 0; kk < 4; ++kk) {
            uint32_t a[4][4];
#pragma unroll
            for (int mi = 0; mi < 4; ++mi) {
                const uint32_t* ap = zb + zOff + mi * 16 * PZ + kk * 8;
                a[mi][0] = ap[0];
                a[mi][1] = ap[8 * PZ];
                a[mi][2] = ap[4];
                a[mi][3] = ap[8 * PZ + 4];
            }
#pragma unroll
            for (int ni = 0; ni < 4; ++ni) {
                const uint32_t* bp = sW + ni * 8 * PW2 + kk * 8;
                uint32_t b0 = bp[0];
                uint32_t b1 = bp[4];
#pragma unroll
                for (int mi = 0; mi < 4; ++mi) mma_f16(acc2[mi][ni], a[mi], b0, b1);
            }
        }

        const int n0 = nc * 64;
#pragma unroll
        for (int mi = 0; mi < 4; ++mi)
#pragma unroll
            for (int ni = 0; ni < 4; ++ni) {
                int r = wr + mi * 16 + gr;
                int n = n0 + wc + ni * 8 + (gc << 1);
                *(float2*)(oT + (size_t)r * C_DIM + n) =
                    make_float2(acc2[mi][ni][0], acc2[mi][ni][1]);
                *(float2*)(oT + (size_t)(r + 8) * C_DIM + n) =
                    make_float2(acc2[mi][ni][2], acc2[mi][ni][3]);
            }
    }
}

extern "C" void kernel_launch(void* const* d_in, const int* in_sizes, int n_in,
                              void* d_out, int out_size) {
    const float* x  = (const float*)d_in[0];
    const int*   e  = (const int*)d_in[1];
    const float* dw = (const float*)d_in[2];
    const float* db = (const float*)d_in[3];
    const float* uw = (const float*)d_in[4];

    cvt_x_kernel<<<(B_DIM * S_DIM * C_DIM) / (256 * 8), 256>>>(x);
    cvt_wd_kernel<<<dim3(M_R * N_E, C_DIM / 64), 256>>>(dw);
    cvt_wu_kernel<<<dim3(M_R * N_E, C_DIM / 64), 256>>>(uw);

    cudaFuncSetAttribute(adapter_kernel,
                         cudaFuncAttributeMaxDynamicSharedMemorySize, SMEM_BYTES);

    dim3 grid(M_R, B_DIM * (S_DIM / TS));
    adapter_kernel<<<grid, THREADS, SMEM_BYTES>>>(e, db, (float*)d_out);
}